// round 1
// baseline (speedup 1.0000x reference)
#include <cuda_runtime.h>
#include <cuda_bf16.h>
#include <math_constants.h>

// Problem constants
#define B_   16
#define L_   1024
#define D_   128
#define H_   8
#define HD_  16
#define ROWS (B_ * L_)          // 16384
#define LN_EPS 1e-5f

// ---------------- scratch (device globals; no allocation allowed) ----------
__device__ float g_qkv[ROWS * 3 * D_];   // 25 MB
__device__ float g_ctx[ROWS * D_];       // 8 MB
__device__ float g_x1 [ROWS * D_];       // 8 MB
__device__ float g_ff1[ROWS * D_];       // 8 MB
__device__ float g_ff2[ROWS * D_];       // 8 MB
__device__ unsigned char g_mask8[(size_t)B_ * L_ * L_];  // 16 MB canonical u8 mask
__device__ int g_mask_is_i32;

// ---------------- mask dtype detection + canonicalization ------------------
// jnp.bool_ may serialize as u8 or i32; detect from byte pattern.
__global__ void detect_mask_kernel(const unsigned char* __restrict__ m) {
    if (threadIdx.x == 0 && blockIdx.x == 0) {
        int i32like = 1;
        for (int i = 0; i < 4096; i += 4) {
            unsigned char b0 = m[i], b1 = m[i+1], b2 = m[i+2], b3 = m[i+3];
            if ((b1 | b2 | b3) != 0 || b0 > 1) { i32like = 0; break; }
        }
        g_mask_is_i32 = i32like;
    }
}

__global__ void convert_mask_kernel(const void* __restrict__ in, int n) {
    int i = blockIdx.x * blockDim.x + threadIdx.x;
    if (i >= n) return;
    unsigned char v;
    if (g_mask_is_i32) v = (((const int*)in)[i] != 0) ? 1 : 0;
    else               v = (((const unsigned char*)in)[i] != 0) ? 1 : 0;
    g_mask8[i] = v;
}

// ---------------- generic fp32 tiled GEMM: C = A@B + bias (opt relu) -------
// A: [M,K] row-major, B: [K,N] row-major. M%64==0, N%64==0, K%16==0.
#define BM 64
#define BN 64
#define BK 16
__global__ __launch_bounds__(256) void gemm_bias_kernel(
    const float* __restrict__ A, const float* __restrict__ Bm,
    const float* __restrict__ bias, float* __restrict__ C,
    int M, int N, int K, int relu)
{
    __shared__ float As[BK][BM];
    __shared__ float Bs[BK][BN];
    const int tx = threadIdx.x % 16;        // col group
    const int ty = threadIdx.x / 16;        // row group
    const int brow = blockIdx.y * BM;
    const int bcol = blockIdx.x * BN;

    float acc[4][4];
    #pragma unroll
    for (int i = 0; i < 4; i++)
        #pragma unroll
        for (int j = 0; j < 4; j++) acc[i][j] = 0.f;

    for (int k0 = 0; k0 < K; k0 += BK) {
        // load A tile (BM x BK) -> As[c][r]
        #pragma unroll
        for (int i = threadIdx.x; i < BM * BK; i += 256) {
            int r = i / BK, c = i % BK;
            As[c][r] = A[(size_t)(brow + r) * K + k0 + c];
        }
        // load B tile (BK x BN)
        #pragma unroll
        for (int i = threadIdx.x; i < BK * BN; i += 256) {
            int r = i / BN, c = i % BN;
            Bs[r][c] = Bm[(size_t)(k0 + r) * N + bcol + c];
        }
        __syncthreads();
        #pragma unroll
        for (int kk = 0; kk < BK; ++kk) {
            float a[4], b[4];
            #pragma unroll
            for (int i = 0; i < 4; i++) a[i] = As[kk][ty * 4 + i];
            #pragma unroll
            for (int j = 0; j < 4; j++) b[j] = Bs[kk][tx * 4 + j];
            #pragma unroll
            for (int i = 0; i < 4; i++)
                #pragma unroll
                for (int j = 0; j < 4; j++) acc[i][j] += a[i] * b[j];
        }
        __syncthreads();
    }
    #pragma unroll
    for (int i = 0; i < 4; i++) {
        int row = brow + ty * 4 + i;
        #pragma unroll
        for (int j = 0; j < 4; j++) {
            int col = bcol + tx * 4 + j;
            float v = acc[i][j] + bias[col];
            if (relu) v = fmaxf(v, 0.f);
            C[(size_t)row * N + col] = v;
        }
    }
}

// ---------------- attention: online softmax, 1 thread = 1 query ------------
// grid: (L/128, B*H), block 128 threads. K/V chunked through smem.
#define CK 128
__global__ __launch_bounds__(128) void attn_kernel(float* __restrict__ ctx)
{
    const int bh = blockIdx.y;
    const int b  = bh / H_;
    const int h  = bh % H_;
    const int q  = blockIdx.x * 128 + threadIdx.x;
    const int tid = threadIdx.x;

    __shared__ float Ks[CK][HD_];
    __shared__ float Vs[CK][HD_];

    // load my query, pre-scaled into log2 domain: s_log2 = (q.k)*scale*log2(e)
    const float qscale = 0.25f * 1.44269504088896f;  // hd^-0.5 * log2(e)
    float qr[HD_];
    {
        const float4* qp = (const float4*)&g_qkv[((size_t)b * L_ + q) * (3 * D_) + h * HD_];
        #pragma unroll
        for (int i = 0; i < HD_ / 4; i++) {
            float4 t = qp[i];
            qr[4*i+0] = t.x * qscale; qr[4*i+1] = t.y * qscale;
            qr[4*i+2] = t.z * qscale; qr[4*i+3] = t.w * qscale;
        }
    }

    float m = -CUDART_INF_F, l = 0.f;
    float acc[HD_];
    #pragma unroll
    for (int i = 0; i < HD_; i++) acc[i] = 0.f;

    const unsigned char* mrow = &g_mask8[((size_t)b * L_ + q) * L_];

    for (int c0 = 0; c0 < L_; c0 += CK) {
        __syncthreads();
        // stage K,V chunk: thread tid loads key row (c0+tid)
        {
            const float4* kp = (const float4*)&g_qkv[((size_t)b * L_ + c0 + tid) * (3 * D_) + D_ + h * HD_];
            const float4* vp = (const float4*)&g_qkv[((size_t)b * L_ + c0 + tid) * (3 * D_) + 2 * D_ + h * HD_];
            float4* ks = (float4*)Ks[tid];
            float4* vs = (float4*)Vs[tid];
            #pragma unroll
            for (int i = 0; i < HD_ / 4; i++) { ks[i] = kp[i]; vs[i] = vp[i]; }
        }
        __syncthreads();

        #pragma unroll 2
        for (int g = 0; g < CK; g += 16) {
            uint4 mw = *(const uint4*)(mrow + c0 + g);
            unsigned w[4] = {mw.x, mw.y, mw.z, mw.w};
            #pragma unroll
            for (int u = 0; u < 4; u++) {
                #pragma unroll
                for (int v8 = 0; v8 < 4; v8++) {
                    if ((w[u] >> (8 * v8)) & 0xFFu) continue;   // masked out
                    int j = g + u * 4 + v8;
                    float s = 0.f;
                    #pragma unroll
                    for (int i = 0; i < HD_; i++) s = fmaf(qr[i], Ks[j][i], s);
                    if (s <= m) {
                        float p = exp2f(s - m);
                        l += p;
                        #pragma unroll
                        for (int i = 0; i < HD_; i++) acc[i] = fmaf(p, Vs[j][i], acc[i]);
                    } else {
                        float corr = exp2f(m - s);
                        l = fmaf(l, corr, 1.f);
                        #pragma unroll
                        for (int i = 0; i < HD_; i++) acc[i] = fmaf(acc[i], corr, Vs[j][i]);
                        m = s;
                    }
                }
            }
        }
    }

    float inv = (l > 0.f) ? (1.f / l) : 0.f;
    float* op = &ctx[((size_t)b * L_ + q) * D_ + h * HD_];
    #pragma unroll
    for (int i = 0; i < HD_; i++) op[i] = acc[i] * inv;
}

// ---------------- fused residual add + LayerNorm ---------------------------
// one block per row; 128 threads, one element each.
__global__ __launch_bounds__(128) void add_ln_kernel(
    const float* __restrict__ a, const float* __restrict__ r,
    const float* __restrict__ gamma, const float* __restrict__ beta,
    float* __restrict__ out)
{
    const int row = blockIdx.x;
    const int t = threadIdx.x;
    const int warp = t >> 5, lane = t & 31;
    __shared__ float red1[4], red2[4];

    float v = a[(size_t)row * D_ + t] + r[(size_t)row * D_ + t];

    float s = v;
    #pragma unroll
    for (int o = 16; o; o >>= 1) s += __shfl_xor_sync(0xffffffffu, s, o);
    if (lane == 0) red1[warp] = s;
    __syncthreads();
    float mu = (red1[0] + red1[1] + red1[2] + red1[3]) * (1.f / D_);

    float c = v - mu;
    float q = c * c;
    #pragma unroll
    for (int o = 16; o; o >>= 1) q += __shfl_xor_sync(0xffffffffu, q, o);
    if (lane == 0) red2[warp] = q;
    __syncthreads();
    float var = (red2[0] + red2[1] + red2[2] + red2[3]) * (1.f / D_);

    out[(size_t)row * D_ + t] = c * rsqrtf(var + LN_EPS) * gamma[t] + beta[t];
}

// ---------------- launch --------------------------------------------------
extern "C" void kernel_launch(void* const* d_in, const int* in_sizes, int n_in,
                              void* d_out, int out_size)
{
    const float* edge_x    = (const float*)d_in[0];
    const void*  edge_mask = d_in[1];
    const float* in_proj_w = (const float*)d_in[2];
    const float* in_proj_b = (const float*)d_in[3];
    const float* w1        = (const float*)d_in[4];
    const float* b1        = (const float*)d_in[5];
    const float* w2        = (const float*)d_in[6];
    const float* b2        = (const float*)d_in[7];
    const float* g1        = (const float*)d_in[8];
    const float* beta1     = (const float*)d_in[9];
    const float* g2        = (const float*)d_in[10];
    const float* beta2     = (const float*)d_in[11];
    float* out = (float*)d_out;

    void *p_qkv, *p_ctx, *p_x1, *p_ff1, *p_ff2;
    cudaGetSymbolAddress(&p_qkv, g_qkv);
    cudaGetSymbolAddress(&p_ctx, g_ctx);
    cudaGetSymbolAddress(&p_x1,  g_x1);
    cudaGetSymbolAddress(&p_ff1, g_ff1);
    cudaGetSymbolAddress(&p_ff2, g_ff2);

    const int nmask = B_ * L_ * L_;

    // 1) mask dtype detect + canonicalize to u8
    detect_mask_kernel<<<1, 32>>>((const unsigned char*)edge_mask);
    convert_mask_kernel<<<(nmask + 255) / 256, 256>>>(edge_mask, nmask);

    // 2) fused QKV projection: [16384,128] @ [128,384]
    {
        dim3 grid(3 * D_ / BN, ROWS / BM);
        gemm_bias_kernel<<<grid, 256>>>(edge_x, in_proj_w, in_proj_b,
                                        (float*)p_qkv, ROWS, 3 * D_, D_, 0);
    }

    // 3) masked attention -> ctx
    {
        dim3 grid(L_ / 128, B_ * H_);
        attn_kernel<<<grid, 128>>>((float*)p_ctx);
    }

    // 4) x1 = LN(edge_x + ctx)
    add_ln_kernel<<<ROWS, 128>>>(edge_x, (const float*)p_ctx, g1, beta1, (float*)p_x1);

    // 5) ff1 = relu(x1 @ w1 + b1)
    {
        dim3 grid(D_ / BN, ROWS / BM);
        gemm_bias_kernel<<<grid, 256>>>((const float*)p_x1, w1, b1,
                                        (float*)p_ff1, ROWS, D_, D_, 1);
    }
    // 6) ff2 = ff1 @ w2 + b2
    {
        dim3 grid(D_ / BN, ROWS / BM);
        gemm_bias_kernel<<<grid, 256>>>((const float*)p_ff1, w2, b2,
                                        (float*)p_ff2, ROWS, D_, D_, 0);
    }
    // 7) out = LN(x1 + ff2)
    add_ln_kernel<<<ROWS, 128>>>((const float*)p_x1, (const float*)p_ff2, g2, beta2, out);
}

// round 3
// speedup vs baseline: 1.3427x; 1.3427x over previous
#include <cuda_runtime.h>
#include <cuda_bf16.h>
#include <math_constants.h>
#include <cstdint>

// Problem constants
#define B_   16
#define L_   1024
#define D_   128
#define H_   8
#define HD_  16
#define ROWS (B_ * L_)          // 16384
#define LN_EPS 1e-5f

// ---------------- scratch (device globals; no allocation allowed) ----------
__device__ float g_qkv[ROWS * 3 * D_];
__device__ float g_ctx[ROWS * D_];
__device__ float g_x1 [ROWS * D_];
__device__ float g_ff1[ROWS * D_];
__device__ float g_ff2[ROWS * D_];
__device__ unsigned char g_mask8[(size_t)B_ * L_ * L_];
__device__ int g_mask_is_i32;

// ============================ helpers ======================================
__device__ __forceinline__ uint32_t smem_u32(const void* p) {
    uint32_t a;
    asm("{ .reg .u64 t; cvta.to.shared.u64 t, %1; cvt.u32.u64 %0, t; }"
        : "=r"(a) : "l"(p));
    return a;
}
__device__ __forceinline__ uint32_t pack_bf16x2(float e, float o) {
    uint32_t r;
    asm("cvt.rn.bf16x2.f32 %0, %1, %2;" : "=r"(r) : "f"(o), "f"(e));
    return r;
}
__device__ __forceinline__ float ex2f(float x) {
    float y; asm("ex2.approx.f32 %0, %1;" : "=f"(y) : "f"(x)); return y;
}
__device__ __forceinline__ float bfr(float x) {          // round to bf16, back to f32
    return __bfloat162float(__float2bfloat16_rn(x));
}
__device__ __forceinline__ float lo16f(uint32_t u) { return __uint_as_float(u << 16); }
__device__ __forceinline__ float hi16f(uint32_t u) { return __uint_as_float(u & 0xFFFF0000u); }

__device__ __forceinline__ void mma_bf16(float* c, const uint32_t* a, uint32_t b0, uint32_t b1) {
    asm volatile("mma.sync.aligned.m16n8k16.row.col.f32.bf16.bf16.f32 "
        "{%0,%1,%2,%3}, {%4,%5,%6,%7}, {%8,%9}, {%0,%1,%2,%3};"
        : "+f"(c[0]), "+f"(c[1]), "+f"(c[2]), "+f"(c[3])
        : "r"(a[0]), "r"(a[1]), "r"(a[2]), "r"(a[3]), "r"(b0), "r"(b1));
}
__device__ __forceinline__ void ldm_x4(uint32_t* r, uint32_t addr) {
    asm volatile("ldmatrix.sync.aligned.m8n8.x4.shared.b16 {%0,%1,%2,%3}, [%4];"
        : "=r"(r[0]), "=r"(r[1]), "=r"(r[2]), "=r"(r[3]) : "r"(addr));
}
__device__ __forceinline__ void ldm_x4_t(uint32_t* r, uint32_t addr) {
    asm volatile("ldmatrix.sync.aligned.m8n8.x4.trans.shared.b16 {%0,%1,%2,%3}, [%4];"
        : "=r"(r[0]), "=r"(r[1]), "=r"(r[2]), "=r"(r[3]) : "r"(addr));
}

// ---------------- mask dtype detection + canonicalization ------------------
__global__ void detect_mask_kernel(const unsigned char* __restrict__ m) {
    if (threadIdx.x == 0 && blockIdx.x == 0) {
        int i32like = 1;
        for (int i = 0; i < 4096; i += 4) {
            unsigned char b0 = m[i], b1 = m[i+1], b2 = m[i+2], b3 = m[i+3];
            if ((b1 | b2 | b3) != 0 || b0 > 1) { i32like = 0; break; }
        }
        g_mask_is_i32 = i32like;
    }
}
__global__ void convert_mask_kernel(const void* __restrict__ in, int n) {
    int i = blockIdx.x * blockDim.x + threadIdx.x;
    if (i >= n) return;
    unsigned char v;
    if (g_mask_is_i32) v = (((const int*)in)[i] != 0) ? 1 : 0;
    else               v = (((const unsigned char*)in)[i] != 0) ? 1 : 0;
    g_mask8[i] = v;
}

// ---------------- generic fp32 tiled GEMM: C = A@B + bias (opt relu) -------
#define BM 64
#define BN 64
#define BK 16
__global__ __launch_bounds__(256) void gemm_bias_kernel(
    const float* __restrict__ A, const float* __restrict__ Bm,
    const float* __restrict__ bias, float* __restrict__ C,
    int M, int N, int K, int relu)
{
    __shared__ float As[BK][BM];
    __shared__ float Bs[BK][BN];
    const int tx = threadIdx.x % 16;
    const int ty = threadIdx.x / 16;
    const int brow = blockIdx.y * BM;
    const int bcol = blockIdx.x * BN;

    float acc[4][4];
    #pragma unroll
    for (int i = 0; i < 4; i++)
        #pragma unroll
        for (int j = 0; j < 4; j++) acc[i][j] = 0.f;

    for (int k0 = 0; k0 < K; k0 += BK) {
        #pragma unroll
        for (int i = threadIdx.x; i < BM * BK; i += 256) {
            int r = i / BK, c = i % BK;
            As[c][r] = A[(size_t)(brow + r) * K + k0 + c];
        }
        #pragma unroll
        for (int i = threadIdx.x; i < BK * BN; i += 256) {
            int r = i / BN, c = i % BN;
            Bs[r][c] = Bm[(size_t)(k0 + r) * N + bcol + c];
        }
        __syncthreads();
        #pragma unroll
        for (int kk = 0; kk < BK; ++kk) {
            float4 av = *(const float4*)&As[kk][ty * 4];
            float4 bv = *(const float4*)&Bs[kk][tx * 4];
            float a[4] = {av.x, av.y, av.z, av.w};
            float b[4] = {bv.x, bv.y, bv.z, bv.w};
            #pragma unroll
            for (int i = 0; i < 4; i++)
                #pragma unroll
                for (int j = 0; j < 4; j++) acc[i][j] += a[i] * b[j];
        }
        __syncthreads();
    }
    #pragma unroll
    for (int i = 0; i < 4; i++) {
        int row = brow + ty * 4 + i;
        #pragma unroll
        for (int j = 0; j < 4; j++) {
            int col = bcol + tx * 4 + j;
            float v = acc[i][j] + bias[col];
            if (relu) v = fmaxf(v, 0.f);
            C[(size_t)row * N + col] = v;
        }
    }
}

// ================= HMMA flash attention ====================================
// Block = (b, h, 128-query tile). 4 warps; warp w owns query rows w*32..w*32+31
// as two m16 tiles. K/V staged per 128-key chunk in smem as bf16 hi/lo with
// 48B row pitch (conflict-free ldmatrix).
#define KROWB 48

__global__ __launch_bounds__(128) void attn_mma_kernel(float* __restrict__ ctx)
{
    __shared__ __align__(16) uint8_t sKh[128 * KROWB];
    __shared__ __align__(16) uint8_t sKl[128 * KROWB];
    __shared__ __align__(16) uint8_t sVh[128 * KROWB];
    __shared__ __align__(16) uint8_t sVl[128 * KROWB];

    const int tid  = threadIdx.x;
    const int lane = tid & 31;
    const int w    = tid >> 5;
    const int b    = blockIdx.y >> 3;
    const int h    = blockIdx.y & 7;
    const int q0   = blockIdx.x << 7;

    const int rq = lane >> 2;            // row-in-tile 0..7
    const int d0 = (lane & 3) * 2;       // col pair base

    const float qscale = 0.25f * 1.44269504088896f;   // hd^-1/2 * log2(e)

    // ---- Q fragments (hi/lo bf16 split), loaded once -----------------------
    uint32_t ah[2][4], al[2][4];
    #pragma unroll
    for (int t = 0; t < 2; t++) {
        int rowA = q0 + w * 32 + t * 16 + rq;
        const float* qb = g_qkv + (size_t)(b * L_ + rowA) * (3 * D_) + h * HD_;
        float2 e0 = *(const float2*)(qb + d0);
        float2 e1 = *(const float2*)(qb + (size_t)8 * (3 * D_) + d0);
        float2 e2 = *(const float2*)(qb + d0 + 8);
        float2 e3 = *(const float2*)(qb + (size_t)8 * (3 * D_) + d0 + 8);
        float v[8] = {e0.x * qscale, e0.y * qscale, e1.x * qscale, e1.y * qscale,
                      e2.x * qscale, e2.y * qscale, e3.x * qscale, e3.y * qscale};
        #pragma unroll
        for (int j = 0; j < 4; j++) {
            float hx = bfr(v[2*j]), hy = bfr(v[2*j+1]);
            ah[t][j] = pack_bf16x2(hx, hy);
            al[t][j] = pack_bf16x2(v[2*j] - hx, v[2*j+1] - hy);
        }
    }

    // mask row base pointers
    const unsigned char* mA[2];
    const unsigned char* mB[2];
    #pragma unroll
    for (int t = 0; t < 2; t++) {
        mA[t] = g_mask8 + ((size_t)(b * L_ + q0 + w * 32 + t * 16 + rq)) * L_;
        mB[t] = mA[t] + (size_t)8 * L_;
    }

    // ldmatrix per-lane address offsets
    const int lm = lane >> 3, lr = lane & 7;
    const uint32_t kOff = (uint32_t)((((lm >> 1) << 3) + lr) * KROWB + ((lm & 1) << 4));
    const uint32_t vOff = (uint32_t)((((lm & 1) << 3) + lr) * KROWB + ((lm >> 1) << 4));
    const uint32_t aKh = smem_u32(sKh) + kOff;
    const uint32_t aKl = smem_u32(sKl) + kOff;
    const uint32_t aVh = smem_u32(sVh) + vOff;
    const uint32_t aVl = smem_u32(sVl) + vOff;

    float o[2][2][4];
    #pragma unroll
    for (int t = 0; t < 2; t++)
        #pragma unroll
        for (int n = 0; n < 2; n++)
            #pragma unroll
            for (int i = 0; i < 4; i++) o[t][n][i] = 0.f;
    float lA[2] = {0.f, 0.f}, lB[2] = {0.f, 0.f};

    for (int ck = 0; ck < L_ / 128; ++ck) {
        const int c0 = ck << 7;

        __syncthreads();
        // ---- stage K/V hi/lo: thread tid handles key row tid ---------------
        {
            const float* kb = g_qkv + (size_t)(b * L_ + c0 + tid) * (3 * D_) + D_ + h * HD_;
            const float* vb = kb + D_;
            uint32_t* kh = (uint32_t*)(sKh + tid * KROWB);
            uint32_t* kl = (uint32_t*)(sKl + tid * KROWB);
            uint32_t* vh = (uint32_t*)(sVh + tid * KROWB);
            uint32_t* vl = (uint32_t*)(sVl + tid * KROWB);
            #pragma unroll
            for (int j = 0; j < 8; j++) {
                float2 kv = *(const float2*)(kb + 2 * j);
                float h0 = bfr(kv.x), h1 = bfr(kv.y);
                kh[j] = pack_bf16x2(h0, h1);
                kl[j] = pack_bf16x2(kv.x - h0, kv.y - h1);
                float2 vv = *(const float2*)(vb + 2 * j);
                float g0 = bfr(vv.x), g1 = bfr(vv.y);
                vh[j] = pack_bf16x2(g0, g1);
                vl[j] = pack_bf16x2(vv.x - g0, vv.y - g1);
            }
        }
        __syncthreads();

        #pragma unroll 2
        for (int s = 0; s < 8; ++s) {
            const uint32_t so = (uint32_t)(s * 16 * KROWB);
            uint32_t kh[4], kl[4], vh[4], vl[4];
            ldm_x4(kh, aKh + so);
            ldm_x4(kl, aKl + so);
            ldm_x4_t(vh, aVh + so);
            ldm_x4_t(vl, aVl + so);
            const int keyb = c0 + s * 16 + d0;

            #pragma unroll
            for (int t = 0; t < 2; t++) {
                float c0f[4] = {0.f, 0.f, 0.f, 0.f};
                float c1f[4] = {0.f, 0.f, 0.f, 0.f};
                // S = Qhi*Khi + Qhi*Klo + Qlo*Khi  (drop lo*lo)
                mma_bf16(c0f, ah[t], kh[0], kh[1]);
                mma_bf16(c0f, ah[t], kl[0], kl[1]);
                mma_bf16(c0f, al[t], kh[0], kh[1]);
                mma_bf16(c1f, ah[t], kh[2], kh[3]);
                mma_bf16(c1f, ah[t], kl[2], kl[3]);
                mma_bf16(c1f, al[t], kh[2], kh[3]);

                uint16_t ma0 = *(const uint16_t*)(mA[t] + keyb);
                uint16_t mb0 = *(const uint16_t*)(mB[t] + keyb);
                uint16_t ma1 = *(const uint16_t*)(mA[t] + keyb + 8);
                uint16_t mb1 = *(const uint16_t*)(mB[t] + keyb + 8);

                float p00 = (ma0 & 0xFF) ? 0.f : ex2f(c0f[0]);
                float p01 = (ma0 >> 8)   ? 0.f : ex2f(c0f[1]);
                float p02 = (mb0 & 0xFF) ? 0.f : ex2f(c0f[2]);
                float p03 = (mb0 >> 8)   ? 0.f : ex2f(c0f[3]);
                float p10 = (ma1 & 0xFF) ? 0.f : ex2f(c1f[0]);
                float p11 = (ma1 >> 8)   ? 0.f : ex2f(c1f[1]);
                float p12 = (mb1 & 0xFF) ? 0.f : ex2f(c1f[2]);
                float p13 = (mb1 >> 8)   ? 0.f : ex2f(c1f[3]);

                uint32_t ap[4];
                ap[0] = pack_bf16x2(p00, p01);   // (row,   k0..)
                ap[1] = pack_bf16x2(p02, p03);   // (row+8, k0..)
                ap[2] = pack_bf16x2(p10, p11);   // (row,   k8..)
                ap[3] = pack_bf16x2(p12, p13);   // (row+8, k8..)

                // accumulate l from ROUNDED p (cancels rounding in normalization)
                lA[t] += lo16f(ap[0]) + hi16f(ap[0]) + lo16f(ap[2]) + hi16f(ap[2]);
                lB[t] += lo16f(ap[1]) + hi16f(ap[1]) + lo16f(ap[3]) + hi16f(ap[3]);

                // O += P*(Vhi+Vlo)
                mma_bf16(o[t][0], ap, vh[0], vh[1]);
                mma_bf16(o[t][0], ap, vl[0], vl[1]);
                mma_bf16(o[t][1], ap, vh[2], vh[3]);
                mma_bf16(o[t][1], ap, vl[2], vl[3]);
            }
        }
    }

    // ---- epilogue: normalize, write ctx ------------------------------------
    #pragma unroll
    for (int t = 0; t < 2; t++) {
        float la = lA[t];
        la += __shfl_xor_sync(0xffffffffu, la, 1);
        la += __shfl_xor_sync(0xffffffffu, la, 2);
        float lb = lB[t];
        lb += __shfl_xor_sync(0xffffffffu, lb, 1);
        lb += __shfl_xor_sync(0xffffffffu, lb, 2);
        float ia = (la > 0.f) ? (1.f / la) : 0.f;
        float ib = (lb > 0.f) ? (1.f / lb) : 0.f;

        int rowA = q0 + w * 32 + t * 16 + rq;
        float* oA = ctx + (size_t)(b * L_ + rowA) * D_ + h * HD_;
        float* oB = oA + (size_t)8 * D_;
        #pragma unroll
        for (int n = 0; n < 2; n++) {
            *(float2*)(oA + n * 8 + d0) = make_float2(o[t][n][0] * ia, o[t][n][1] * ia);
            *(float2*)(oB + n * 8 + d0) = make_float2(o[t][n][2] * ib, o[t][n][3] * ib);
        }
    }
}

// ---------------- fused residual add + LayerNorm ---------------------------
__global__ __launch_bounds__(128) void add_ln_kernel(
    const float* __restrict__ a, const float* __restrict__ r,
    const float* __restrict__ gamma, const float* __restrict__ beta,
    float* __restrict__ out)
{
    const int row = blockIdx.x;
    const int t = threadIdx.x;
    const int warp = t >> 5, lane = t & 31;
    __shared__ float red1[4], red2[4];

    float v = a[(size_t)row * D_ + t] + r[(size_t)row * D_ + t];

    float s = v;
    #pragma unroll
    for (int o = 16; o; o >>= 1) s += __shfl_xor_sync(0xffffffffu, s, o);
    if (lane == 0) red1[warp] = s;
    __syncthreads();
    float mu = (red1[0] + red1[1] + red1[2] + red1[3]) * (1.f / D_);

    float c = v - mu;
    float q = c * c;
    #pragma unroll
    for (int o = 16; o; o >>= 1) q += __shfl_xor_sync(0xffffffffu, q, o);
    if (lane == 0) red2[warp] = q;
    __syncthreads();
    float var = (red2[0] + red2[1] + red2[2] + red2[3]) * (1.f / D_);

    out[(size_t)row * D_ + t] = c * rsqrtf(var + LN_EPS) * gamma[t] + beta[t];
}

// ---------------- launch --------------------------------------------------
extern "C" void kernel_launch(void* const* d_in, const int* in_sizes, int n_in,
                              void* d_out, int out_size)
{
    const float* edge_x    = (const float*)d_in[0];
    const void*  edge_mask = d_in[1];
    const float* in_proj_w = (const float*)d_in[2];
    const float* in_proj_b = (const float*)d_in[3];
    const float* w1        = (const float*)d_in[4];
    const float* b1        = (const float*)d_in[5];
    const float* w2        = (const float*)d_in[6];
    const float* b2        = (const float*)d_in[7];
    const float* g1        = (const float*)d_in[8];
    const float* beta1     = (const float*)d_in[9];
    const float* g2        = (const float*)d_in[10];
    const float* beta2     = (const float*)d_in[11];
    float* out = (float*)d_out;

    void *p_qkv, *p_ctx, *p_x1, *p_ff1, *p_ff2;
    cudaGetSymbolAddress(&p_qkv, g_qkv);
    cudaGetSymbolAddress(&p_ctx, g_ctx);
    cudaGetSymbolAddress(&p_x1,  g_x1);
    cudaGetSymbolAddress(&p_ff1, g_ff1);
    cudaGetSymbolAddress(&p_ff2, g_ff2);

    const int nmask = B_ * L_ * L_;

    // 1) mask dtype detect + canonicalize to u8
    detect_mask_kernel<<<1, 32>>>((const unsigned char*)edge_mask);
    convert_mask_kernel<<<(nmask + 255) / 256, 256>>>(edge_mask, nmask);

    // 2) fused QKV projection: [16384,128] @ [128,384]
    {
        dim3 grid(3 * D_ / BN, ROWS / BM);
        gemm_bias_kernel<<<grid, 256>>>(edge_x, in_proj_w, in_proj_b,
                                        (float*)p_qkv, ROWS, 3 * D_, D_, 0);
    }

    // 3) masked attention -> ctx (HMMA flash)
    {
        dim3 grid(L_ / 128, B_ * H_);
        attn_mma_kernel<<<grid, 128>>>((float*)p_ctx);
    }

    // 4) x1 = LN(edge_x + ctx)
    add_ln_kernel<<<ROWS, 128>>>(edge_x, (const float*)p_ctx, g1, beta1, (float*)p_x1);

    // 5) ff1 = relu(x1 @ w1 + b1)
    {
        dim3 grid(D_ / BN, ROWS / BM);
        gemm_bias_kernel<<<grid, 256>>>((const float*)p_x1, w1, b1,
                                        (float*)p_ff1, ROWS, D_, D_, 1);
    }
    // 6) ff2 = ff1 @ w2 + b2
    {
        dim3 grid(D_ / BN, ROWS / BM);
        gemm_bias_kernel<<<grid, 256>>>((const float*)p_ff1, w2, b2,
                                        (float*)p_ff2, ROWS, D_, D_, 0);
    }
    // 7) out = LN(x1 + ff2)
    add_ln_kernel<<<ROWS, 128>>>((const float*)p_x1, (const float*)p_ff2, g2, beta2, out);
}